// round 1
// baseline (speedup 1.0000x reference)
#include <cuda_runtime.h>
#include <cstddef>

// Problem constants
#define B_  8
#define C_  512
#define HW_ 64
#define NPIX_ 4096
#define IN_ 32

// ---------------- scratch (device globals; no runtime allocation) ----------------
__device__ float g_S[B_ * C_ * 9];                 // border-aware channel sums
__device__ float g_filt1[B_ * IN_ * IN_ * 9];      // predicted filter 1
__device__ float g_filt2[B_ * IN_ * IN_ * 9];      // predicted filter 2
__device__ float g_c0[B_ * IN_ * NPIX_];           // ds conv output
__device__ float g_c1[B_ * IN_ * NPIX_];           // after filt1 + lrelu
__device__ float g_c2[B_ * IN_ * NPIX_];           // after filt2

// ============================================================================
// Kernel 1: style reduction.
// For each (b, channel): compute T (total sum), R0/R63 (first/last row sums),
// C0/C63 (first/last col sums), corners -> 9 clipped sums S[ky][kx].
// mean(conv3x3_SAME(style,w))[o] == (1/4096) * sum_{i,ky,kx} w[o,i,ky,kx]*S[i,ky,kx]
// ============================================================================
__global__ void style_reduce_kernel(const float* __restrict__ style,
                                    float* __restrict__ S)
{
    const int i = blockIdx.x;     // channel
    const int b = blockIdx.y;     // batch
    const int t = threadIdx.x;    // 256 threads
    const float* p = style + ((size_t)(b * C_ + i)) * NPIX_;

    float T = 0.f, R0 = 0.f, R63 = 0.f, Ca = 0.f, Cb = 0.f;
    #pragma unroll
    for (int k = 0; k < 4; k++) {
        int idx4 = t + k * 256;                          // 0..1023 float4s
        float4 v = reinterpret_cast<const float4*>(p)[idx4];
        int y  = idx4 >> 4;                              // row (16 float4 per row)
        int xq = idx4 & 15;
        float s = v.x + v.y + v.z + v.w;
        T += s;
        if (y == 0)   R0  += s;
        if (y == 63)  R63 += s;
        if (xq == 0)  Ca  += v.x;                        // col 0
        if (xq == 15) Cb  += v.w;                        // col 63
    }

    __shared__ float red[5][8];
    float vals[5] = {T, R0, R63, Ca, Cb};
    const int lane = t & 31, wid = t >> 5;
    #pragma unroll
    for (int j = 0; j < 5; j++) {
        float v = vals[j];
        #pragma unroll
        for (int off = 16; off; off >>= 1) v += __shfl_xor_sync(0xffffffffu, v, off);
        if (lane == 0) red[j][wid] = v;
    }
    __syncthreads();

    if (t == 0) {
        float tv[5];
        #pragma unroll
        for (int j = 0; j < 5; j++) {
            float s = 0.f;
            #pragma unroll
            for (int wq = 0; wq < 8; wq++) s += red[j][wq];
            tv[j] = s;
        }
        const float c00 = p[0];
        const float c0e = p[63];
        const float ce0 = p[63 * 64];
        const float cee = p[63 * 64 + 63];
        float* out = S + (size_t)(b * C_ + i) * 9;
        #pragma unroll
        for (int ky = 0; ky < 3; ky++) {
            #pragma unroll
            for (int kx = 0; kx < 3; kx++) {
                float s = tv[0];
                if (ky == 0) s -= tv[2];   // drop last row
                if (ky == 2) s -= tv[1];   // drop first row
                if (kx == 0) s -= tv[4];   // drop last col
                if (kx == 2) s -= tv[3];   // drop first col
                if (ky == 0 && kx == 0) s += cee;
                if (ky == 0 && kx == 2) s += ce0;
                if (ky == 2 && kx == 0) s += c0e;
                if (ky == 2 && kx == 2) s += c00;
                out[ky * 3 + kx] = s;
            }
        }
    }
}

// ============================================================================
// Kernel 2: filter prediction (both predictors fused). One block per batch.
// Phase 1: pooled[o] = (sum_{i,k} cw[o,i,k] * S[b,i,k]) / 4096 + cb[o]
// Phase 2: filt[j]   = fb[j] + sum_o pooled[o] * fw[j, o]
// ============================================================================
__global__ void predict_kernel(const float* __restrict__ S,
                               const float* __restrict__ cw1, const float* __restrict__ cb1,
                               const float* __restrict__ fw1, const float* __restrict__ fb1,
                               const float* __restrict__ cw2, const float* __restrict__ cb2,
                               const float* __restrict__ fw2, const float* __restrict__ fb2,
                               float* __restrict__ filt1, float* __restrict__ filt2)
{
    const int b = blockIdx.x;
    const int t = threadIdx.x;   // 256
    __shared__ float red[256];
    __shared__ float pooled[64];

    const float* Sb = S + (size_t)b * C_ * 9;

    // phase 1: 64 outputs (0..31 -> predictor1, 32..63 -> predictor2), 4 partials each
    {
        const int o = t & 63;
        const int part = t >> 6;                  // 0..3, 128 channels each
        const int oo = o & 31;
        const float* cw = (o < 32) ? cw1 : cw2;
        const float* cwp = cw + (size_t)oo * (C_ * 9) + part * 128 * 9;
        const float* Sp  = Sb + part * 128 * 9;
        float s0 = 0.f, s1 = 0.f;
        #pragma unroll 4
        for (int k = 0; k < 1152; k += 2) {
            s0 = fmaf(cwp[k],     Sp[k],     s0);
            s1 = fmaf(cwp[k + 1], Sp[k + 1], s1);
        }
        red[t] = s0 + s1;
    }
    __syncthreads();
    if (t < 64) {
        float tot = red[t] + red[t + 64] + red[t + 128] + red[t + 192];
        float cb = (t < 32) ? cb1[t] : cb2[t - 32];
        pooled[t] = tot * (1.f / 4096.f) + cb;
    }
    __syncthreads();

    // phase 2: 2*9216 filter coefficients
    for (int j = t; j < 2 * 9216; j += 256) {
        const bool first = (j < 9216);
        const int jj = first ? j : j - 9216;
        const float* fw = first ? fw1 : fw2;
        const float* fb = first ? fb1 : fb2;
        const float* pp = pooled + (first ? 0 : 32);
        float v = fb[jj];
        const float4* fw4 = reinterpret_cast<const float4*>(fw + (size_t)jj * 32);
        #pragma unroll
        for (int q = 0; q < 8; q++) {
            float4 wv = fw4[q];
            v = fmaf(wv.x, pp[q * 4 + 0], v);
            v = fmaf(wv.y, pp[q * 4 + 1], v);
            v = fmaf(wv.z, pp[q * 4 + 2], v);
            v = fmaf(wv.w, pp[q * 4 + 3], v);
        }
        (first ? filt1 : filt2)[(size_t)b * 9216 + jj] = v;
    }
}

// ============================================================================
// Kernel 3 (generic): 3x3 SAME conv, fp32 direct, register-tiled.
// Block: 32x8 spatial tile, 32 output channels, 256 threads.
// Thread: 8 horizontally-adjacent pixels x 4 output channels (32 accumulators).
// K-loop over input channels in chunks of 8 through shared memory.
// Weights broadcast within a warp (all lanes share the o-group).
// ============================================================================
template <bool LRELU, bool RESID>
__global__ void __launch_bounds__(256, 2)
conv3x3_kernel(const float* __restrict__ x, const float* __restrict__ w,
               const float* __restrict__ bias, const float* __restrict__ resid,
               float* __restrict__ y, int cin, int octot, int wbstride)
{
    __shared__ __align__(16) float s_in[8 * 10 * 36];   // 8 ch x (8+2) rows x (32+2 pad->36)
    __shared__ __align__(16) float s_w[8 * 32 * 12];    // 8 ch x 32 oc x (9 pad->12)

    const int b    = blockIdx.z;
    const int ocb  = blockIdx.y * 32;
    const int tx   = (blockIdx.x & 1) * 32;
    const int ty   = (blockIdx.x >> 1) * 8;
    const int t    = threadIdx.x;
    const int og   = t >> 5;              // warp id == output-channel group (4 oc)
    const int lane = t & 31;
    const int row  = lane >> 2;           // 0..7
    const int segx = (lane & 3) * 8;      // 0,8,16,24

    const float* xb = x + (size_t)b * cin * NPIX_;
    const float* wb = w + (size_t)b * wbstride;

    float acc[4][8];
    #pragma unroll
    for (int i = 0; i < 4; i++)
        #pragma unroll
        for (int j = 0; j < 8; j++) acc[i][j] = 0.f;

    const int nchunk = cin >> 3;
    for (int ch = 0; ch < nchunk; ch++) {
        const int c0 = ch << 3;
        __syncthreads();
        // stage input tile (with halo, zero-padded at image borders)
        for (int idx = t; idx < 2720; idx += 256) {
            int c  = idx / 340;
            int r  = idx - c * 340;
            int ry = r / 34;
            int rx = r - ry * 34;
            int gy = ty + ry - 1;
            int gx = tx + rx - 1;
            float v = 0.f;
            if ((unsigned)gy < 64u && (unsigned)gx < 64u)
                v = xb[(size_t)(c0 + c) * NPIX_ + gy * 64 + gx];
            s_in[(c * 10 + ry) * 36 + rx] = v;
        }
        // stage weights, transposed to [c][o][k] (k padded to 12)
        for (int idx = t; idx < 2304; idx += 256) {
            int c = idx / 288;
            int r = idx - c * 288;
            int o = r / 9;
            int k = r - o * 9;
            s_w[(c * 32 + o) * 12 + k] =
                wb[((size_t)(ocb + o) * cin + (c0 + c)) * 9 + k];
        }
        __syncthreads();

        #pragma unroll
        for (int c = 0; c < 8; c++) {
            float xr[3][10];
            const float* xp = &s_in[(c * 10 + row) * 36 + segx];
            #pragma unroll
            for (int ky = 0; ky < 3; ky++) {
                float4 a = *reinterpret_cast<const float4*>(xp + ky * 36);
                float4 d = *reinterpret_cast<const float4*>(xp + ky * 36 + 4);
                float2 e = *reinterpret_cast<const float2*>(xp + ky * 36 + 8);
                xr[ky][0] = a.x; xr[ky][1] = a.y; xr[ky][2] = a.z; xr[ky][3] = a.w;
                xr[ky][4] = d.x; xr[ky][5] = d.y; xr[ky][6] = d.z; xr[ky][7] = d.w;
                xr[ky][8] = e.x; xr[ky][9] = e.y;
            }
            const float* wp = &s_w[(c * 32 + og * 4) * 12];
            #pragma unroll
            for (int o4 = 0; o4 < 4; o4++) {
                float4 w0 = *reinterpret_cast<const float4*>(wp + o4 * 12);
                float4 w1 = *reinterpret_cast<const float4*>(wp + o4 * 12 + 4);
                float  w8 = wp[o4 * 12 + 8];
                float wk[9] = {w0.x, w0.y, w0.z, w0.w, w1.x, w1.y, w1.z, w1.w, w8};
                #pragma unroll
                for (int ky = 0; ky < 3; ky++) {
                    #pragma unroll
                    for (int p = 0; p < 8; p++) {
                        float a0 = fmaf(wk[ky * 3 + 0], xr[ky][p],     acc[o4][p]);
                        a0       = fmaf(wk[ky * 3 + 1], xr[ky][p + 1], a0);
                        acc[o4][p] = fmaf(wk[ky * 3 + 2], xr[ky][p + 2], a0);
                    }
                }
            }
        }
    }

    // epilogue
    const int gy  = ty + row;
    const int gx0 = tx + segx;
    #pragma unroll
    for (int o4 = 0; o4 < 4; o4++) {
        const int o = ocb + og * 4 + o4;
        const float bv = bias ? bias[o] : 0.f;
        const size_t base = ((size_t)(b * octot + o) * 64 + gy) * 64 + gx0;
        #pragma unroll
        for (int h = 0; h < 2; h++) {
            float u0 = acc[o4][h * 4 + 0] + bv;
            float u1 = acc[o4][h * 4 + 1] + bv;
            float u2 = acc[o4][h * 4 + 2] + bv;
            float u3 = acc[o4][h * 4 + 3] + bv;
            if (LRELU) {
                u0 = (u0 >= 0.f) ? u0 : 0.2f * u0;
                u1 = (u1 >= 0.f) ? u1 : 0.2f * u1;
                u2 = (u2 >= 0.f) ? u2 : 0.2f * u2;
                u3 = (u3 >= 0.f) ? u3 : 0.2f * u3;
            }
            float4 v = make_float4(u0, u1, u2, u3);
            if (RESID) {
                float4 rv = *reinterpret_cast<const float4*>(resid + base + h * 4);
                v.x += rv.x; v.y += rv.y; v.z += rv.z; v.w += rv.w;
            }
            *reinterpret_cast<float4*>(y + base + h * 4) = v;
        }
    }
}

// ============================================================================
extern "C" void kernel_launch(void* const* d_in, const int* in_sizes, int n_in,
                              void* d_out, int out_size)
{
    const float* content = (const float*)d_in[0];
    const float* style   = (const float*)d_in[1];
    const float* ds_w    = (const float*)d_in[2];
    const float* ds_b    = (const float*)d_in[3];
    const float* up_w    = (const float*)d_in[4];
    const float* up_b    = (const float*)d_in[5];
    const float* f1_cw   = (const float*)d_in[6];
    const float* f1_cb   = (const float*)d_in[7];
    const float* f1_fw   = (const float*)d_in[8];
    const float* f1_fb   = (const float*)d_in[9];
    const float* f2_cw   = (const float*)d_in[10];
    const float* f2_cb   = (const float*)d_in[11];
    const float* f2_fw   = (const float*)d_in[12];
    const float* f2_fb   = (const float*)d_in[13];
    float* out = (float*)d_out;

    float *pS, *pF1, *pF2, *pC0, *pC1, *pC2;
    cudaGetSymbolAddress((void**)&pS,  g_S);
    cudaGetSymbolAddress((void**)&pF1, g_filt1);
    cudaGetSymbolAddress((void**)&pF2, g_filt2);
    cudaGetSymbolAddress((void**)&pC0, g_c0);
    cudaGetSymbolAddress((void**)&pC1, g_c1);
    cudaGetSymbolAddress((void**)&pC2, g_c2);

    // 1) style border-aware reduction
    style_reduce_kernel<<<dim3(C_, B_), 256>>>(style, pS);

    // 2) both filter predictions
    predict_kernel<<<B_, 256>>>(pS, f1_cw, f1_cb, f1_fw, f1_fb,
                                    f2_cw, f2_cb, f2_fw, f2_fb, pF1, pF2);

    // 3) ds conv: content [8,512,64,64] -> c0 [8,32,64,64]
    conv3x3_kernel<false, false><<<dim3(16, 1, B_), 256>>>(
        content, ds_w, ds_b, nullptr, pC0, C_, IN_, 0);

    // 4) dynamic conv 1 + LeakyReLU(0.2)
    conv3x3_kernel<true, false><<<dim3(16, 1, B_), 256>>>(
        pC0, pF1, nullptr, nullptr, pC1, IN_, IN_, IN_ * IN_ * 9);

    // 5) dynamic conv 2
    conv3x3_kernel<false, false><<<dim3(16, 1, B_), 256>>>(
        pC1, pF2, nullptr, nullptr, pC2, IN_, IN_, IN_ * IN_ * 9);

    // 6) up conv + residual: out = content + conv3x3(c2, up_w, up_b)
    conv3x3_kernel<false, true><<<dim3(16, 16, B_), 256>>>(
        pC2, up_w, up_b, content, out, IN_, C_, 0);
}

// round 2
// speedup vs baseline: 2.0020x; 2.0020x over previous
#include <cuda_runtime.h>
#include <cuda_bf16.h>
#include <cstdint>
#include <cstddef>

// Problem constants
#define B_  8
#define C_  512
#define NPIX_ 4096
#define IN_ 32

// ---------------- scratch (device globals; no runtime allocation) ----------------
__device__ float g_S[B_ * C_ * 9];
__device__ float g_filt1[B_ * IN_ * IN_ * 9];
__device__ float g_filt2[B_ * IN_ * IN_ * 9];
__device__ float g_c0[B_ * IN_ * NPIX_];
__device__ float g_c1[B_ * IN_ * NPIX_];
__device__ float g_c2[B_ * IN_ * NPIX_];
__device__ float g_part[3 * B_ * IN_ * NPIX_];            // ds split-K partials
__device__ __nv_bfloat16 g_wt_ds[9 * 32 * C_ * 16 / 16];  // [9][32][32][16] = 147456
__device__ __nv_bfloat16 g_wt_up[9 * 2 * C_ * 16];        // [9][2][512][16] = 147456

// ============================================================================
// Style reduction (unchanged)
// ============================================================================
__global__ void style_reduce_kernel(const float* __restrict__ style,
                                    float* __restrict__ S)
{
    const int i = blockIdx.x, b = blockIdx.y, t = threadIdx.x;
    const float* p = style + ((size_t)(b * C_ + i)) * NPIX_;

    float T = 0.f, R0 = 0.f, R63 = 0.f, Ca = 0.f, Cb = 0.f;
    #pragma unroll
    for (int k = 0; k < 4; k++) {
        int idx4 = t + k * 256;
        float4 v = reinterpret_cast<const float4*>(p)[idx4];
        int y = idx4 >> 4, xq = idx4 & 15;
        float s = v.x + v.y + v.z + v.w;
        T += s;
        if (y == 0)   R0  += s;
        if (y == 63)  R63 += s;
        if (xq == 0)  Ca  += v.x;
        if (xq == 15) Cb  += v.w;
    }
    __shared__ float red[5][8];
    float vals[5] = {T, R0, R63, Ca, Cb};
    const int lane = t & 31, wid = t >> 5;
    #pragma unroll
    for (int j = 0; j < 5; j++) {
        float v = vals[j];
        #pragma unroll
        for (int off = 16; off; off >>= 1) v += __shfl_xor_sync(0xffffffffu, v, off);
        if (lane == 0) red[j][wid] = v;
    }
    __syncthreads();
    if (t == 0) {
        float tv[5];
        #pragma unroll
        for (int j = 0; j < 5; j++) {
            float s = 0.f;
            #pragma unroll
            for (int wq = 0; wq < 8; wq++) s += red[j][wq];
            tv[j] = s;
        }
        const float c00 = p[0], c0e = p[63], ce0 = p[63 * 64], cee = p[63 * 64 + 63];
        float* out = S + (size_t)(b * C_ + i) * 9;
        #pragma unroll
        for (int ky = 0; ky < 3; ky++)
            #pragma unroll
            for (int kx = 0; kx < 3; kx++) {
                float s = tv[0];
                if (ky == 0) s -= tv[2];
                if (ky == 2) s -= tv[1];
                if (kx == 0) s -= tv[4];
                if (kx == 2) s -= tv[3];
                if (ky == 0 && kx == 0) s += cee;
                if (ky == 0 && kx == 2) s += ce0;
                if (ky == 2 && kx == 0) s += c0e;
                if (ky == 2 && kx == 2) s += c00;
                out[ky * 3 + kx] = s;
            }
    }
}

// ============================================================================
// Filter prediction (unchanged)
// ============================================================================
__global__ void predict_kernel(const float* __restrict__ S,
                               const float* __restrict__ cw1, const float* __restrict__ cb1,
                               const float* __restrict__ fw1, const float* __restrict__ fb1,
                               const float* __restrict__ cw2, const float* __restrict__ cb2,
                               const float* __restrict__ fw2, const float* __restrict__ fb2,
                               float* __restrict__ filt1, float* __restrict__ filt2)
{
    const int b = blockIdx.x, t = threadIdx.x;
    __shared__ float red[256];
    __shared__ float pooled[64];
    const float* Sb = S + (size_t)b * C_ * 9;
    {
        const int o = t & 63, part = t >> 6, oo = o & 31;
        const float* cw = (o < 32) ? cw1 : cw2;
        const float* cwp = cw + (size_t)oo * (C_ * 9) + part * 128 * 9;
        const float* Sp  = Sb + part * 128 * 9;
        float s0 = 0.f, s1 = 0.f;
        #pragma unroll 4
        for (int k = 0; k < 1152; k += 2) {
            s0 = fmaf(cwp[k], Sp[k], s0);
            s1 = fmaf(cwp[k + 1], Sp[k + 1], s1);
        }
        red[t] = s0 + s1;
    }
    __syncthreads();
    if (t < 64) {
        float tot = red[t] + red[t + 64] + red[t + 128] + red[t + 192];
        float cb = (t < 32) ? cb1[t] : cb2[t - 32];
        pooled[t] = tot * (1.f / 4096.f) + cb;
    }
    __syncthreads();
    for (int j = t; j < 2 * 9216; j += 256) {
        const bool first = (j < 9216);
        const int jj = first ? j : j - 9216;
        const float* fw = first ? fw1 : fw2;
        const float* fb = first ? fb1 : fb2;
        const float* pp = pooled + (first ? 0 : 32);
        float v = fb[jj];
        const float4* fw4 = reinterpret_cast<const float4*>(fw + (size_t)jj * 32);
        #pragma unroll
        for (int q = 0; q < 8; q++) {
            float4 wv = fw4[q];
            v = fmaf(wv.x, pp[q * 4 + 0], v);
            v = fmaf(wv.y, pp[q * 4 + 1], v);
            v = fmaf(wv.z, pp[q * 4 + 2], v);
            v = fmaf(wv.w, pp[q * 4 + 3], v);
        }
        (first ? filt1 : filt2)[(size_t)b * 9216 + jj] = v;
    }
}

// ============================================================================
// Weight transpose: W[oc][ic][tap] fp32 -> Wt[tap][ic/16][oc][16] bf16
// ============================================================================
__global__ void wtrans_kernel(const float* __restrict__ w, __nv_bfloat16* __restrict__ wt,
                              int cin, int cout)
{
    int idx = blockIdx.x * 256 + threadIdx.x;
    int total = cout * cin * 9;
    if (idx >= total) return;
    int i16 = idx & 15;
    int oc  = (idx >> 4) % cout;
    int rest = idx / (16 * cout);
    int nch = cin >> 4;
    int chunk = rest % nch;
    int tap = rest / nch;
    int ic = chunk * 16 + i16;
    wt[idx] = __float2bfloat16_rn(w[((size_t)oc * cin + ic) * 9 + tap]);
}

// ============================================================================
// Tensor-core conv3x3 via tap-decomposed implicit GEMM.
// CTA: M = MT output channels, N = 256 pixels (4 rows x 64 cols).
// Per ic-chunk of 16: stage raw input tile [6][66][16->pad18] bf16 (interleaved
// ic-fastest so all 9 tap shifts read mma-B fragments directly), stage 9 tap
// weight slices [9][MT][16] bf16, then 9 x mma.m16n8k16 per warp tile.
// ============================================================================
__device__ __forceinline__ void mma16816(float* c, const uint32_t* a, const uint32_t* b)
{
    asm volatile(
        "mma.sync.aligned.m16n8k16.row.col.f32.bf16.bf16.f32 "
        "{%0,%1,%2,%3}, {%4,%5,%6,%7}, {%8,%9}, {%0,%1,%2,%3};\n"
        : "+f"(c[0]), "+f"(c[1]), "+f"(c[2]), "+f"(c[3])
        : "r"(a[0]), "r"(a[1]), "r"(a[2]), "r"(a[3]), "r"(b[0]), "r"(b[1]));
}

template <int MT, int NFRAG, bool SPLIT, bool RESID>
__global__ void __launch_bounds__(256)
conv_mma_kernel(const float* __restrict__ x, const __nv_bfloat16* __restrict__ wt,
                const float* __restrict__ bias, const float* __restrict__ resid,
                float* __restrict__ y, int cin, int cout)
{
    __shared__ __align__(16) __nv_bfloat16 s_x[6 * 66 * 18];  // raw tile, ic padded 16->18
    __shared__ __align__(16) __nv_bfloat16 s_a[9 * MT * 16];  // weights per chunk

    const int b  = blockIdx.z;
    const int ty = blockIdx.x * 4;                // 4 output rows per CTA
    const int t  = threadIdx.x;
    const int wid = t >> 5, lane = t & 31;
    const int g = lane >> 2, t4 = lane & 3;

    int chunk0, nch, ocb;
    float* yb;
    if (SPLIT) {
        int s = blockIdx.y;
        chunk0 = s * 11; nch = (s == 2) ? 10 : 11; ocb = 0;
        yb = y + ((size_t)(s * B_ + b)) * (IN_ * NPIX_);
    } else {
        ocb = blockIdx.y * MT; chunk0 = 0; nch = cin >> 4;
        yb = y + (size_t)b * cout * NPIX_;
    }

    // warp tiling: MT=32 -> 8 warps across N (32 px each); MT=64 -> 2(M) x 4(N)
    const int wm = (MT == 32) ? 0 : (wid >> 2) * 32;
    const int nb = (MT == 32) ? wid * 32 : (wid & 3) * 64;

    // per-lane B fragment pixel bases (u32 index units: pixel*9 + t4)
    int bBase[NFRAG];
    #pragma unroll
    for (int f = 0; f < NFRAG; f++) {
        int n = nb + f * 8 + g;
        int r = n >> 6, cc = n & 63;
        bBase[f] = (r * 66 + cc) * 9 + t4;
    }

    float acc[2][NFRAG][4];
    #pragma unroll
    for (int mf = 0; mf < 2; mf++)
        #pragma unroll
        for (int f = 0; f < NFRAG; f++)
            #pragma unroll
            for (int q = 0; q < 4; q++) acc[mf][f][q] = 0.f;

    const float* xb = x + (size_t)b * cin * NPIX_;
    const uint32_t* s_xu = reinterpret_cast<const uint32_t*>(s_x);
    const uint32_t* s_au = reinterpret_cast<const uint32_t*>(s_a);
    uint32_t* s_au_w = reinterpret_cast<uint32_t*>(s_a);
    const int nch16 = cin >> 4;

    for (int c = chunk0; c < chunk0 + nch; c++) {
        __syncthreads();
        // ---- stage raw input tile: rows ty-1..ty+4, cols -1..64, 16 ic ----
        for (int idx = t; idx < 6 * 66 * 16; idx += 256) {
            int rowid = idx / 66;            // 0..95
            int x_ = idx - rowid * 66;       // 0..65
            int ic = rowid / 6;
            int y_ = rowid - ic * 6;
            int gy = ty + y_ - 1;
            int gx = x_ - 1;
            float v = 0.f;
            if ((unsigned)gy < 64u && (unsigned)gx < 64u)
                v = xb[(size_t)(c * 16 + ic) * NPIX_ + gy * 64 + gx];
            s_x[(y_ * 66 + x_) * 18 + ic] = __float2bfloat16_rn(v);
        }
        // ---- stage weights: 9 taps x [MT][16] ----
        {
            const int per = MT * 8;   // u32 per tap slice
            for (int idx = t; idx < 9 * per; idx += 256) {
                int tap = idx / per;
                int j = idx - tap * per;
                const uint32_t* src = reinterpret_cast<const uint32_t*>(
                    wt + ((size_t)(tap * nch16 + c) * cout + ocb) * 16);
                s_au_w[tap * per + j] = src[j];
            }
        }
        __syncthreads();

        #pragma unroll
        for (int tap = 0; tap < 9; tap++) {
            const int dy = tap / 3, dx = tap - dy * 3;
            // A fragments
            uint32_t a[2][4];
            #pragma unroll
            for (int mf = 0; mf < 2; mf++) {
                int oc0 = wm + mf * 16 + g;
                int base = (tap * MT + oc0) * 8 + t4;
                a[mf][0] = s_au[base];
                a[mf][1] = s_au[base + 8 * 8];   // row +8 -> +8 oc * 8 u32
                a[mf][2] = s_au[base + 4];       // k +8
                a[mf][3] = s_au[base + 8 * 8 + 4];
            }
            // B fragments
            const int shift = (dy * 66 + dx) * 9;
            uint32_t bf[NFRAG][2];
            #pragma unroll
            for (int f = 0; f < NFRAG; f++) {
                int u = bBase[f] + shift;
                bf[f][0] = s_xu[u];
                bf[f][1] = s_xu[u + 4];
            }
            // MMAs
            #pragma unroll
            for (int mf = 0; mf < 2; mf++)
                #pragma unroll
                for (int f = 0; f < NFRAG; f++)
                    mma16816(acc[mf][f], a[mf], bf[f]);
        }
    }

    // ---- epilogue ----
    #pragma unroll
    for (int mf = 0; mf < 2; mf++) {
        int oc0 = ocb + wm + mf * 16 + g;   // rows g and g+8
        #pragma unroll
        for (int rr = 0; rr < 2; rr++) {
            int oc = oc0 + rr * 8;
            float bv = (RESID && bias) ? bias[oc] : 0.f;
            #pragma unroll
            for (int f = 0; f < NFRAG; f++) {
                int n = nb + f * 8 + t4 * 2;
                size_t off = (size_t)oc * NPIX_ + (size_t)(ty * 64) + n;
                float2 v;
                v.x = acc[mf][f][rr * 2 + 0] + bv;
                v.y = acc[mf][f][rr * 2 + 1] + bv;
                if (RESID) {
                    float2 rv = *reinterpret_cast<const float2*>(
                        resid + (size_t)b * cout * NPIX_ + off);
                    v.x += rv.x; v.y += rv.y;
                }
                *reinterpret_cast<float2*>(yb + off) = v;
            }
        }
    }
}

// ============================================================================
// Combine ds split-K partials + bias
// ============================================================================
__global__ void combine_kernel(const float* __restrict__ part,
                               const float* __restrict__ bias,
                               float* __restrict__ out)
{
    int i = blockIdx.x * 256 + threadIdx.x;     // float4 index, total 262144
    const float4* p0 = reinterpret_cast<const float4*>(part);
    const float4* p1 = p0 + 262144;
    const float4* p2 = p1 + 262144;
    float4 a = p0[i], bq = p1[i], cq = p2[i];
    float bv = bias[(i >> 10) & 31];
    float4 r;
    r.x = a.x + bq.x + cq.x + bv;
    r.y = a.y + bq.y + cq.y + bv;
    r.z = a.z + bq.z + cq.z + bv;
    r.w = a.w + bq.w + cq.w + bv;
    reinterpret_cast<float4*>(out)[i] = r;
}

// ============================================================================
// fp32 direct conv (kept for the two small dynamic convs)
// ============================================================================
template <bool LRELU>
__global__ void __launch_bounds__(256, 2)
conv3x3_kernel(const float* __restrict__ x, const float* __restrict__ w,
               float* __restrict__ y, int cin, int octot, int wbstride)
{
    __shared__ __align__(16) float s_in[8 * 10 * 36];
    __shared__ __align__(16) float s_w[8 * 32 * 12];

    const int b = blockIdx.z;
    const int ocb = blockIdx.y * 32;
    const int tx = (blockIdx.x & 1) * 32;
    const int ty = (blockIdx.x >> 1) * 8;
    const int t = threadIdx.x;
    const int og = t >> 5, lane = t & 31;
    const int row = lane >> 2, segx = (lane & 3) * 8;

    const float* xb = x + (size_t)b * cin * NPIX_;
    const float* wb = w + (size_t)b * wbstride;

    float acc[4][8];
    #pragma unroll
    for (int i = 0; i < 4; i++)
        #pragma unroll
        for (int j = 0; j < 8; j++) acc[i][j] = 0.f;

    const int nchunk = cin >> 3;
    for (int ch = 0; ch < nchunk; ch++) {
        const int c0 = ch << 3;
        __syncthreads();
        for (int idx = t; idx < 2720; idx += 256) {
            int c = idx / 340, r = idx - c * 340;
            int ry = r / 34, rx = r - ry * 34;
            int gy = ty + ry - 1, gx = tx + rx - 1;
            float v = 0.f;
            if ((unsigned)gy < 64u && (unsigned)gx < 64u)
                v = xb[(size_t)(c0 + c) * NPIX_ + gy * 64 + gx];
            s_in[(c * 10 + ry) * 36 + rx] = v;
        }
        for (int idx = t; idx < 2304; idx += 256) {
            int c = idx / 288, r = idx - c * 288;
            int o = r / 9, k = r - o * 9;
            s_w[(c * 32 + o) * 12 + k] = wb[((size_t)(ocb + o) * cin + (c0 + c)) * 9 + k];
        }
        __syncthreads();
        #pragma unroll
        for (int c = 0; c < 8; c++) {
            float xr[3][10];
            const float* xp = &s_in[(c * 10 + row) * 36 + segx];
            #pragma unroll
            for (int ky = 0; ky < 3; ky++) {
                float4 a = *reinterpret_cast<const float4*>(xp + ky * 36);
                float4 d = *reinterpret_cast<const float4*>(xp + ky * 36 + 4);
                float2 e = *reinterpret_cast<const float2*>(xp + ky * 36 + 8);
                xr[ky][0] = a.x; xr[ky][1] = a.y; xr[ky][2] = a.z; xr[ky][3] = a.w;
                xr[ky][4] = d.x; xr[ky][5] = d.y; xr[ky][6] = d.z; xr[ky][7] = d.w;
                xr[ky][8] = e.x; xr[ky][9] = e.y;
            }
            const float* wp = &s_w[(c * 32 + og * 4) * 12];
            #pragma unroll
            for (int o4 = 0; o4 < 4; o4++) {
                float4 w0 = *reinterpret_cast<const float4*>(wp + o4 * 12);
                float4 w1 = *reinterpret_cast<const float4*>(wp + o4 * 12 + 4);
                float w8 = wp[o4 * 12 + 8];
                float wk[9] = {w0.x, w0.y, w0.z, w0.w, w1.x, w1.y, w1.z, w1.w, w8};
                #pragma unroll
                for (int ky = 0; ky < 3; ky++)
                    #pragma unroll
                    for (int p = 0; p < 8; p++) {
                        float a0 = fmaf(wk[ky * 3 + 0], xr[ky][p], acc[o4][p]);
                        a0 = fmaf(wk[ky * 3 + 1], xr[ky][p + 1], a0);
                        acc[o4][p] = fmaf(wk[ky * 3 + 2], xr[ky][p + 2], a0);
                    }
            }
        }
    }
    const int gy = ty + row, gx0 = tx + segx;
    #pragma unroll
    for (int o4 = 0; o4 < 4; o4++) {
        const int o = ocb + og * 4 + o4;
        const size_t base = ((size_t)(b * octot + o) * 64 + gy) * 64 + gx0;
        #pragma unroll
        for (int h = 0; h < 2; h++) {
            float u0 = acc[o4][h * 4 + 0], u1 = acc[o4][h * 4 + 1];
            float u2 = acc[o4][h * 4 + 2], u3 = acc[o4][h * 4 + 3];
            if (LRELU) {
                u0 = (u0 >= 0.f) ? u0 : 0.2f * u0;
                u1 = (u1 >= 0.f) ? u1 : 0.2f * u1;
                u2 = (u2 >= 0.f) ? u2 : 0.2f * u2;
                u3 = (u3 >= 0.f) ? u3 : 0.2f * u3;
            }
            *reinterpret_cast<float4*>(y + base + h * 4) = make_float4(u0, u1, u2, u3);
        }
    }
}

// ============================================================================
extern "C" void kernel_launch(void* const* d_in, const int* in_sizes, int n_in,
                              void* d_out, int out_size)
{
    const float* content = (const float*)d_in[0];
    const float* style   = (const float*)d_in[1];
    const float* ds_w    = (const float*)d_in[2];
    const float* ds_b    = (const float*)d_in[3];
    const float* up_w    = (const float*)d_in[4];
    const float* up_b    = (const float*)d_in[5];
    const float* f1_cw   = (const float*)d_in[6];
    const float* f1_cb   = (const float*)d_in[7];
    const float* f1_fw   = (const float*)d_in[8];
    const float* f1_fb   = (const float*)d_in[9];
    const float* f2_cw   = (const float*)d_in[10];
    const float* f2_cb   = (const float*)d_in[11];
    const float* f2_fw   = (const float*)d_in[12];
    const float* f2_fb   = (const float*)d_in[13];
    float* out = (float*)d_out;

    float *pS, *pF1, *pF2, *pC0, *pC1, *pC2, *pPart;
    __nv_bfloat16 *pWds, *pWup;
    cudaGetSymbolAddress((void**)&pS,  g_S);
    cudaGetSymbolAddress((void**)&pF1, g_filt1);
    cudaGetSymbolAddress((void**)&pF2, g_filt2);
    cudaGetSymbolAddress((void**)&pC0, g_c0);
    cudaGetSymbolAddress((void**)&pC1, g_c1);
    cudaGetSymbolAddress((void**)&pC2, g_c2);
    cudaGetSymbolAddress((void**)&pPart, g_part);
    cudaGetSymbolAddress((void**)&pWds, g_wt_ds);
    cudaGetSymbolAddress((void**)&pWup, g_wt_up);

    // 1) style reduction + filter prediction
    style_reduce_kernel<<<dim3(C_, B_), 256>>>(style, pS);
    predict_kernel<<<B_, 256>>>(pS, f1_cw, f1_cb, f1_fw, f1_fb,
                                    f2_cw, f2_cb, f2_fw, f2_fb, pF1, pF2);

    // 2) transpose big-conv weights to bf16 mma layout
    wtrans_kernel<<<576, 256>>>(ds_w, pWds, C_, IN_);
    wtrans_kernel<<<576, 256>>>(up_w, pWup, IN_, C_);

    // 3) ds conv (tensor core, split-K=3 over ic) -> partials
    conv_mma_kernel<32, 4, true, false><<<dim3(16, 3, B_), 256>>>(
        content, pWds, nullptr, nullptr, pPart, C_, IN_);

    // 4) combine partials + bias -> c0
    combine_kernel<<<1024, 256>>>(pPart, ds_b, pC0);

    // 5) dynamic conv 1 + LeakyReLU
    conv3x3_kernel<true><<<dim3(16, 1, B_), 256>>>(pC0, pF1, pC1, IN_, IN_, IN_ * IN_ * 9);

    // 6) dynamic conv 2
    conv3x3_kernel<false><<<dim3(16, 1, B_), 256>>>(pC1, pF2, pC2, IN_, IN_, IN_ * IN_ * 9);

    // 7) up conv (tensor core) + bias + residual
    conv_mma_kernel<64, 8, false, true><<<dim3(16, 8, B_), 256>>>(
        pC2, pWup, up_b, content, out, IN_, C_);
}